// round 11
// baseline (speedup 1.0000x reference)
#include <cuda_runtime.h>
#include <cuda_bf16.h>
#include <cstdint>
#include <math.h>

#define NB 128
#define NL 4096
#define ND 128
#define NT64 8192     // 64-row L tiles: NB * (NL/64)

// ---------------- scratch ----------------
__device__ float g_qb[NB * ND];
__device__ float g_scores[NB * NL];

__device__ __forceinline__ uint32_t smem_u32(const void* p) {
    uint32_t a;
    asm("{ .reg .u64 t; cvta.to.shared.u64 t, %1; cvt.u32.u64 %0, t; }" : "=r"(a) : "l"(p));
    return a;
}
__device__ __forceinline__ void ldsm_x4(uint32_t& r0, uint32_t& r1, uint32_t& r2, uint32_t& r3,
                                        uint32_t addr) {
    asm volatile("ldmatrix.sync.aligned.m8n8.x4.shared.b16 {%0,%1,%2,%3}, [%4];"
                 : "=r"(r0), "=r"(r1), "=r"(r2), "=r"(r3) : "r"(addr));
}
__device__ __forceinline__ void mma16816(float* c, const uint32_t* a, const uint32_t* b) {
    asm volatile("mma.sync.aligned.m16n8k16.row.col.f32.bf16.bf16.f32 "
                 "{%0,%1,%2,%3}, {%4,%5,%6,%7}, {%8,%9}, {%0,%1,%2,%3};"
                 : "+f"(c[0]), "+f"(c[1]), "+f"(c[2]), "+f"(c[3])
                 : "r"(a[0]), "r"(a[1]), "r"(a[2]), "r"(a[3]), "r"(b[0]), "r"(b[1]));
}
__device__ __forceinline__ float fast_pow(float x, float e) {
    float l, r;
    asm("lg2.approx.f32 %0, %1;" : "=f"(l) : "f"(x));
    l *= e;
    asm("ex2.approx.f32 %0, %1;" : "=f"(r) : "f"(l));
    return r;
}
// split float2 -> packed hi bf16x2 / lo bf16x2 (low half = first element)
__device__ __forceinline__ void split2(float2 x, uint32_t& hp, uint32_t& lp) {
    __nv_bfloat16 h0 = __float2bfloat16(x.x), h1 = __float2bfloat16(x.y);
    __nv_bfloat16 q0 = __float2bfloat16(x.x - __bfloat162float(h0));
    __nv_bfloat16 q1 = __float2bfloat16(x.y - __bfloat162float(h1));
    hp = ((uint32_t)__bfloat16_as_ushort(h1) << 16) | __bfloat16_as_ushort(h0);
    lp = ((uint32_t)__bfloat16_as_ushort(q1) << 16) | __bfloat16_as_ushort(q0);
}
__device__ __forceinline__ void split4(float4 x, uint2& hp, uint2& lp) {
    float2 a = make_float2(x.x, x.y), b = make_float2(x.z, x.w);
    split2(a, hp.x, lp.x);
    split2(b, hp.y, lp.y);
}

// ============ kernel 0: qb = Wr2·(Wf target + b) + bias_r ============
__global__ __launch_bounds__(512, 1)
void k_prep(const float* __restrict__ target, const float* __restrict__ Wf_w,
            const float* __restrict__ Wf_b, const float* __restrict__ Wr2,
            const float* __restrict__ bias_r) {
    int bx = blockIdx.x, t = threadIdx.x;
    int lane = t & 31, w = t >> 5;           // 16 warps
    __shared__ float q[64];
    float4 tg4 = ((const float4*)(target + bx * ND))[lane];
    #pragma unroll
    for (int r = 0; r < 4; r++) {
        int e = w + r * 16;
        float4 wf = ((const float4*)(Wf_w + e * ND))[lane];
        float p = tg4.x * wf.x + tg4.y * wf.y + tg4.z * wf.z + tg4.w * wf.w;
        #pragma unroll
        for (int o = 16; o; o >>= 1) p += __shfl_xor_sync(0xFFFFFFFFu, p, o);
        if (lane == 0) q[e] = p + Wf_b[e];
    }
    __syncthreads();
    float2 q2 = ((const float2*)q)[lane];
    #pragma unroll
    for (int r = 0; r < 8; r++) {
        int d = w + r * 16;
        float2 w2 = ((const float2*)(Wr2 + d * 64))[lane];
        float p = q2.x * w2.x + q2.y * w2.y;
        #pragma unroll
        for (int o = 16; o; o >>= 1) p += __shfl_xor_sync(0xFFFFFFFFu, p, o);
        if (lane == 0) g_qb[bx * ND + d] = p + bias_r[d];
    }
}

// ============ kernel 1: persistent split-bf16 GEMM, A fragments direct from gmem ============
// 256 threads (8 warps: wr=w>>2 in {0,1}, wc=w&3). 64-row L tiles.
// B (Wr1 hi/lo) in smem once per CTA; A built in registers from __ldg.
#define ROWB 272
#define SB_HI 0
#define SB_LO 34816
#define SM_PART 69632          // 64 rows x 4 wc floats = 1024 B
#define SM_W3   70656          // 512 B
#define SM_TOTAL 71168

__global__ __launch_bounds__(256, 2)
void k_gemm(const float* __restrict__ R, const float* __restrict__ Wr1,
            const float* __restrict__ Wr3) {
    extern __shared__ char smem[];
    uint32_t sb = smem_u32(smem);
    int tid = threadIdx.x, lane = tid & 31, w = tid >> 5;
    int wr = w >> 2, wc = w & 3;
    int g = lane >> 2, t2 = (lane & 3) * 2;

    // ---- B tiles (hi/lo split of Wr1) once per CTA ----
    {
        const float4* src = (const float4*)Wr1;
        #pragma unroll
        for (int i = 0; i < 16; i++) {
            int idx = tid + i * 256;            // 0..4095 float4
            int row = idx >> 5, c4 = idx & 31;
            uint2 hp, lp;
            split4(src[idx], hp, lp);
            uint32_t off = row * ROWB + c4 * 8;
            *(uint2*)(smem + SB_HI + off) = hp;
            *(uint2*)(smem + SB_LO + off) = lp;
        }
        if (tid < ND) ((float*)(smem + SM_W3))[tid] = Wr3[tid];
    }
    __syncthreads();

    uint32_t b_hi = sb + SB_HI + (wc * 32 + (lane >> 4) * 8 + (lane & 7)) * ROWB
                    + ((lane >> 3) & 1) * 16;
    uint32_t b_lo = b_hi + (SB_LO - SB_HI);

    int stride = gridDim.x;
    for (int t = blockIdx.x; t < NT64; t += stride) {
        int b = t >> 6, l0 = (t & 63) << 6;
        // warp's A row pointer: row = l0 + wr*32 + g (+ mt*16, +8)
        const float* Abase = R + ((size_t)b * NL + l0 + wr * 32 + g) * ND;

        float acc[2][4][4];
        #pragma unroll
        for (int mt = 0; mt < 2; mt++)
            #pragma unroll
            for (int nt = 0; nt < 4; nt++)
                #pragma unroll
                for (int k = 0; k < 4; k++) acc[mt][nt][k] = 0.0f;

        #pragma unroll
        for (int ks = 0; ks < 8; ks++) {
            uint32_t bh[4][2], bl[4][2];
            ldsm_x4(bh[0][0], bh[0][1], bh[1][0], bh[1][1], b_hi + ks * 32);
            ldsm_x4(bh[2][0], bh[2][1], bh[3][0], bh[3][1], b_hi + 16 * ROWB + ks * 32);
            ldsm_x4(bl[0][0], bl[0][1], bl[1][0], bl[1][1], b_lo + ks * 32);
            ldsm_x4(bl[2][0], bl[2][1], bl[3][0], bl[3][1], b_lo + 16 * ROWB + ks * 32);
            int c0 = ks * 16 + t2;
            #pragma unroll
            for (int mt = 0; mt < 2; mt++) {
                const float* Ar = Abase + (size_t)(mt * 16) * ND;
                float2 x0 = __ldg((const float2*)(Ar + c0));               // A[g][c0..c0+1]
                float2 x1 = __ldg((const float2*)(Ar + (size_t)8 * ND + c0));   // A[g+8][..]
                float2 x2 = __ldg((const float2*)(Ar + c0 + 8));           // A[g][c0+8..]
                float2 x3 = __ldg((const float2*)(Ar + (size_t)8 * ND + c0 + 8));
                uint32_t ah[4], al[4];
                split2(x0, ah[0], al[0]);
                split2(x1, ah[1], al[1]);
                split2(x2, ah[2], al[2]);
                split2(x3, ah[3], al[3]);
                #pragma unroll
                for (int nt = 0; nt < 4; nt++) {
                    mma16816(acc[mt][nt], ah, bh[nt]);
                    mma16816(acc[mt][nt], ah, bl[nt]);
                    mma16816(acc[mt][nt], al, bh[nt]);
                }
            }
        }

        // ---- epilogue: score[m] = sum_c relu(h+qb)*w3 ----
        {
            const float* w3s = (const float*)(smem + SM_W3);
            float* part = (float*)(smem + SM_PART);
            const float* qbb = g_qb + b * ND;
            int c0base = wc * 32 + t2;
            #pragma unroll
            for (int mt = 0; mt < 2; mt++) {
                float vlo = 0.0f, vhi = 0.0f;
                #pragma unroll
                for (int nt = 0; nt < 4; nt++) {
                    int c0 = c0base + nt * 8, c1 = c0 + 1;
                    float q0 = __ldg(qbb + c0), q1 = __ldg(qbb + c1);
                    float t0 = w3s[c0], t1 = w3s[c1];
                    vlo += fmaxf(acc[mt][nt][0] + q0, 0.0f) * t0
                         + fmaxf(acc[mt][nt][1] + q1, 0.0f) * t1;
                    vhi += fmaxf(acc[mt][nt][2] + q0, 0.0f) * t0
                         + fmaxf(acc[mt][nt][3] + q1, 0.0f) * t1;
                }
                vlo += __shfl_xor_sync(0xFFFFFFFFu, vlo, 1);
                vlo += __shfl_xor_sync(0xFFFFFFFFu, vlo, 2);
                vhi += __shfl_xor_sync(0xFFFFFFFFu, vhi, 1);
                vhi += __shfl_xor_sync(0xFFFFFFFFu, vhi, 2);
                if ((lane & 3) == 0) {
                    int rlo = wr * 32 + mt * 16 + g;
                    part[rlo * 4 + wc] = vlo;
                    part[(rlo + 8) * 4 + wc] = vhi;
                }
            }
        }
        __syncthreads();
        if (tid < 64) {
            const float* part = (const float*)(smem + SM_PART);
            float s = part[tid * 4] + part[tid * 4 + 1] + part[tid * 4 + 2] + part[tid * 4 + 3];
            g_scores[b * NL + l0 + tid] = s;
        }
        __syncthreads();   // part consumed before next tile overwrites
    }
}

// ============ kernel 2: entmax bisection (candidate-compacted) + sparse sum ============
__global__ __launch_bounds__(512, 1)
void k_entmax(const float* __restrict__ R, const float* __restrict__ alpha,
              float* __restrict__ out) {
    __shared__ float cval[NL];
    __shared__ unsigned short cidx[NL];
    __shared__ float red[16];
    __shared__ int cnt;
    __shared__ float part[512];

    int b = blockIdx.x, t = threadIdx.x;
    int lane = t & 31, w = t >> 5;
    float am1 = alpha[b] - 1.0f;
    float inv = 1.0f / am1;

    if (t == 0) cnt = 0;

    float v[8];
    float mx = -3.4e38f;
    #pragma unroll
    for (int i = 0; i < 8; i++) {
        v[i] = g_scores[b * NL + t + i * 512] * am1;
        mx = fmaxf(mx, v[i]);
    }
    #pragma unroll
    for (int o = 16; o; o >>= 1) mx = fmaxf(mx, __shfl_xor_sync(0xFFFFFFFFu, mx, o));
    if (lane == 0) red[w] = mx;
    __syncthreads();
    mx = red[0];
    #pragma unroll
    for (int i = 1; i < 16; i++) mx = fmaxf(mx, red[i]);
    __syncthreads();

    float thr = mx - 1.0f;
    #pragma unroll
    for (int i = 0; i < 8; i++) {
        bool p = v[i] > thr;
        unsigned m = __ballot_sync(0xFFFFFFFFu, p);
        int base = 0;
        if (lane == 0 && m) base = atomicAdd(&cnt, __popc(m));
        base = __shfl_sync(0xFFFFFFFFu, base, 0);
        if (p) {
            int off = base + __popc(m & ((1u << lane) - 1u));
            cval[off] = v[i];
            cidx[off] = (unsigned short)(t + i * 512);
        }
    }
    __syncthreads();
    int K = cnt;

    float tau_lo = mx - 1.0f;
    float tau_hi = mx - exp2f(-12.0f * am1);
    float dm = tau_hi - tau_lo;

    float s = 0.0f;
    for (int j = t; j < K; j += 512) {
        float x = cval[j] - tau_lo;
        if (x > 0.0f) s += fast_pow(x, inv);
    }
    #pragma unroll
    for (int o = 16; o; o >>= 1) s += __shfl_xor_sync(0xFFFFFFFFu, s, o);
    if (lane == 0) red[w] = s;
    __syncthreads();
    float f_lo = -1.0f;
    #pragma unroll
    for (int i = 0; i < 16; i++) f_lo += red[i];
    __syncthreads();

    float tau_m = tau_lo;
    for (int it = 0; it < 50; it++) {
        dm *= 0.5f;
        tau_m = tau_lo + dm;
        s = 0.0f;
        for (int j = t; j < K; j += 512) {
            float x = cval[j] - tau_m;
            if (x > 0.0f) s += fast_pow(x, inv);
        }
        #pragma unroll
        for (int o = 16; o; o >>= 1) s += __shfl_xor_sync(0xFFFFFFFFu, s, o);
        if (lane == 0) red[w] = s;
        __syncthreads();
        float f_m = -1.0f;
        #pragma unroll
        for (int i = 0; i < 16; i++) f_m += red[i];
        __syncthreads();
        if (f_m * f_lo >= 0.0f) tau_lo = tau_m;
    }

    s = 0.0f;
    for (int j = t; j < K; j += 512) {
        float x = cval[j] - tau_m;
        float p = (x > 0.0f) ? fast_pow(x, inv) : 0.0f;
        cval[j] = p;
        s += p;
    }
    #pragma unroll
    for (int o = 16; o; o >>= 1) s += __shfl_xor_sync(0xFFFFFFFFu, s, o);
    if (lane == 0) red[w] = s;
    __syncthreads();
    float S = 0.0f;
    #pragma unroll
    for (int i = 0; i < 16; i++) S += red[i];
    __syncthreads();
    float invS = 1.0f / S;

    int gq = t >> 7, d = t & 127;
    const float* Rb = R + (size_t)b * NL * ND;
    float acc = 0.0f;
    for (int j = gq; j < K; j += 4) {
        float wv = cval[j];
        if (wv != 0.0f) {
            int l = cidx[j];
            acc += wv * Rb[(size_t)l * ND + d];
        }
    }
    part[t] = acc;
    __syncthreads();

    float myr = 0.0f;
    if (t < ND) {
        float r = (part[t] + part[128 + t] + part[256 + t] + part[384 + t]) * invS;
        float e = (r > 0.0f) ? r : 1.6732632423543772f * expm1f(r);
        myr = 1.0507009873554805f * e;
    }
    float nsq = myr * myr;
    #pragma unroll
    for (int o = 16; o; o >>= 1) nsq += __shfl_xor_sync(0xFFFFFFFFu, nsq, o);
    if (lane == 0) red[w] = nsq;
    __syncthreads();
    float tot = 0.0f;
    #pragma unroll
    for (int i = 0; i < 16; i++) tot += red[i];
    if (t < ND) out[b * ND + t] = myr / sqrtf(tot);
}

// ============ launch ============
extern "C" void kernel_launch(void* const* d_in, const int* in_sizes, int n_in,
                              void* d_out, int out_size) {
    const float* R      = (const float*)d_in[0];
    const float* alpha  = (const float*)d_in[1];
    const float* target = (const float*)d_in[2];
    const float* Wr1    = (const float*)d_in[3];
    const float* Wr2    = (const float*)d_in[4];
    const float* Wr3    = (const float*)d_in[5];
    const float* bias_r = (const float*)d_in[6];
    const float* Wf_w   = (const float*)d_in[7];
    const float* Wf_b   = (const float*)d_in[8];
    float* out = (float*)d_out;

    int nsm = 0;
    cudaDeviceGetAttribute(&nsm, cudaDevAttrMultiProcessorCount, 0);
    if (nsm <= 0) nsm = 148;
    int grid = 2 * nsm;
    if (grid > NT64) grid = NT64;

    cudaFuncSetAttribute(k_gemm, cudaFuncAttributeMaxDynamicSharedMemorySize, SM_TOTAL);

    k_prep<<<NB, 512>>>(target, Wf_w, Wf_b, Wr2, bias_r);
    k_gemm<<<grid, 256, SM_TOTAL>>>(R, Wr1, Wr3);
    k_entmax<<<NB, 512>>>(R, alpha, out);
}

// round 12
// speedup vs baseline: 1.3072x; 1.3072x over previous
#include <cuda_runtime.h>
#include <cuda_fp16.h>
#include <cstdint>
#include <math.h>

#define NB 128
#define NL 4096
#define ND 128
#define NTILES 4096   // 128-row L tiles

// ---------------- scratch ----------------
__device__ float g_qb[NB * ND];
__device__ float g_scores[NB * NL];

__device__ __forceinline__ uint32_t smem_u32(const void* p) {
    uint32_t a;
    asm("{ .reg .u64 t; cvta.to.shared.u64 t, %1; cvt.u32.u64 %0, t; }" : "=r"(a) : "l"(p));
    return a;
}
__device__ __forceinline__ void ldsm_x4(uint32_t& r0, uint32_t& r1, uint32_t& r2, uint32_t& r3,
                                        uint32_t addr) {
    asm volatile("ldmatrix.sync.aligned.m8n8.x4.shared.b16 {%0,%1,%2,%3}, [%4];"
                 : "=r"(r0), "=r"(r1), "=r"(r2), "=r"(r3) : "r"(addr));
}
__device__ __forceinline__ void mma16816h(float* c, const uint32_t* a, const uint32_t* b) {
    asm volatile("mma.sync.aligned.m16n8k16.row.col.f32.f16.f16.f32 "
                 "{%0,%1,%2,%3}, {%4,%5,%6,%7}, {%8,%9}, {%0,%1,%2,%3};"
                 : "+f"(c[0]), "+f"(c[1]), "+f"(c[2]), "+f"(c[3])
                 : "r"(a[0]), "r"(a[1]), "r"(a[2]), "r"(a[3]), "r"(b[0]), "r"(b[1]));
}
__device__ __forceinline__ float fast_pow(float x, float e) {
    float l, r;
    asm("lg2.approx.f32 %0, %1;" : "=f"(l) : "f"(x));
    l *= e;
    asm("ex2.approx.f32 %0, %1;" : "=f"(r) : "f"(l));
    return r;
}
// pack 2 floats -> fp16x2
__device__ __forceinline__ uint32_t pack_h2(float x, float y) {
    __half h0 = __float2half_rn(x), h1 = __float2half_rn(y);
    return ((uint32_t)__half_as_ushort(h1) << 16) | __half_as_ushort(h0);
}
// hi/lo fp16 split of float2
__device__ __forceinline__ void split2h(float2 x, uint32_t& hp, uint32_t& lp) {
    __half h0 = __float2half_rn(x.x), h1 = __float2half_rn(x.y);
    __half q0 = __float2half_rn(x.x - __half2float(h0));
    __half q1 = __float2half_rn(x.y - __half2float(h1));
    hp = ((uint32_t)__half_as_ushort(h1) << 16) | __half_as_ushort(h0);
    lp = ((uint32_t)__half_as_ushort(q1) << 16) | __half_as_ushort(q0);
}

// ============ kernel 0: qb = Wr2·(Wf target + b) + bias_r ============
__global__ __launch_bounds__(512, 1)
void k_prep(const float* __restrict__ target, const float* __restrict__ Wf_w,
            const float* __restrict__ Wf_b, const float* __restrict__ Wr2,
            const float* __restrict__ bias_r) {
    int bx = blockIdx.x, t = threadIdx.x;
    int lane = t & 31, w = t >> 5;           // 16 warps
    __shared__ float q[64];
    float4 tg4 = ((const float4*)(target + bx * ND))[lane];
    #pragma unroll
    for (int r = 0; r < 4; r++) {
        int e = w + r * 16;
        float4 wf = ((const float4*)(Wf_w + e * ND))[lane];
        float p = tg4.x * wf.x + tg4.y * wf.y + tg4.z * wf.z + tg4.w * wf.w;
        #pragma unroll
        for (int o = 16; o; o >>= 1) p += __shfl_xor_sync(0xFFFFFFFFu, p, o);
        if (lane == 0) q[e] = p + Wf_b[e];
    }
    __syncthreads();
    float2 q2 = ((const float2*)q)[lane];
    #pragma unroll
    for (int r = 0; r < 8; r++) {
        int d = w + r * 16;
        float2 w2 = ((const float2*)(Wr2 + d * 64))[lane];
        float p = q2.x * w2.x + q2.y * w2.y;
        #pragma unroll
        for (int o = 16; o; o >>= 1) p += __shfl_xor_sync(0xFFFFFFFFu, p, o);
        if (lane == 0) g_qb[bx * ND + d] = p + bias_r[d];
    }
}

// ============ kernel 1: persistent fp16 2-product GEMM + fused score epilogue ============
// 512 threads (16 warps). Warp tile 32x32 (wr=w>>2, wc=w&3). 128-row L tiles.
// A: single fp16 in smem (register-prefetched). B: Wr1 hi/lo fp16, loaded once.
#define ROWB 272
#define SA    0
#define SB_HI 34816
#define SB_LO 69632
#define SM_PART 104448
#define SM_W3   106496
#define SM_TOTAL 107008

__device__ __forceinline__ void ldg_tile(float4* v, const float* __restrict__ R,
                                         int tile, int tid) {
    int b = tile >> 5, l0 = (tile & 31) << 7;
    const float4* src = (const float4*)(R + ((size_t)b * NL + l0) * ND);
    #pragma unroll
    for (int i = 0; i < 8; i++) v[i] = src[tid + i * 512];
}
__device__ __forceinline__ void cvt_store(char* smem, const float4* v, int tid) {
    #pragma unroll
    for (int i = 0; i < 8; i++) {
        int idx = tid + i * 512;
        int row = idx >> 5, c4 = idx & 31;
        float4 x = v[i];
        uint2 hp;
        hp.x = pack_h2(x.x, x.y);
        hp.y = pack_h2(x.z, x.w);
        *(uint2*)(smem + SA + row * ROWB + c4 * 8) = hp;
    }
}

__global__ __launch_bounds__(512, 1)
void k_gemm(const float* __restrict__ R, const float* __restrict__ Wr1,
            const float* __restrict__ Wr3) {
    extern __shared__ char smem[];
    uint32_t sb = smem_u32(smem);
    int tid = threadIdx.x, lane = tid & 31, w = tid >> 5;
    int wr = w >> 2, wc = w & 3;

    // ---- B tiles: hi/lo fp16 split of Wr1, once per CTA ----
    {
        const float4* src = (const float4*)Wr1;
        #pragma unroll
        for (int i = 0; i < 8; i++) {
            int idx = tid + i * 512;               // 0..4095 float4
            int row = idx >> 5, c4 = idx & 31;
            float4 x = src[idx];
            uint2 hp, lp;
            split2h(make_float2(x.x, x.y), hp.x, lp.x);
            split2h(make_float2(x.z, x.w), hp.y, lp.y);
            uint32_t off = row * ROWB + c4 * 8;
            *(uint2*)(smem + SB_HI + off) = hp;
            *(uint2*)(smem + SB_LO + off) = lp;
        }
        if (tid < ND) ((float*)(smem + SM_W3))[tid] = Wr3[tid];
    }

    uint32_t a_p = sb + SA + (wr * 32 + (lane & 15)) * ROWB + (lane >> 4) * 16;
    uint32_t b_hi = sb + SB_HI + (wc * 32 + (lane >> 4) * 8 + (lane & 7)) * ROWB
                    + ((lane >> 3) & 1) * 16;
    uint32_t b_lo = b_hi + (SB_LO - SB_HI);

    int stride = gridDim.x;
    int t = blockIdx.x;
    float4 v[8];
    if (t < NTILES) {
        ldg_tile(v, R, t, tid);
        cvt_store(smem, v, tid);
    }

    while (t < NTILES) {
        __syncthreads();                            // A (and first-iter B) visible
        int tn = t + stride;
        if (tn < NTILES) ldg_tile(v, R, tn, tid);   // register prefetch of next tile

        int b = t >> 5, l0 = (t & 31) << 7;

        float acc[2][4][4];
        #pragma unroll
        for (int mt = 0; mt < 2; mt++)
            #pragma unroll
            for (int nt = 0; nt < 4; nt++)
                #pragma unroll
                for (int k = 0; k < 4; k++) acc[mt][nt][k] = 0.0f;

        #pragma unroll
        for (int ks = 0; ks < 8; ks++) {
            uint32_t bh[4][2], bl[4][2];
            ldsm_x4(bh[0][0], bh[0][1], bh[1][0], bh[1][1], b_hi + ks * 32);
            ldsm_x4(bh[2][0], bh[2][1], bh[3][0], bh[3][1], b_hi + 16 * ROWB + ks * 32);
            ldsm_x4(bl[0][0], bl[0][1], bl[1][0], bl[1][1], b_lo + ks * 32);
            ldsm_x4(bl[2][0], bl[2][1], bl[3][0], bl[3][1], b_lo + 16 * ROWB + ks * 32);
            #pragma unroll
            for (int mt = 0; mt < 2; mt++) {
                uint32_t a4[4];
                ldsm_x4(a4[0], a4[1], a4[2], a4[3], a_p + mt * 16 * ROWB + ks * 32);
                #pragma unroll
                for (int nt = 0; nt < 4; nt++) {
                    mma16816h(acc[mt][nt], a4, bh[nt]);
                    mma16816h(acc[mt][nt], a4, bl[nt]);
                }
            }
        }

        // ---- epilogue: score[m] = sum_c relu(h+qb)*w3 ----
        {
            const float* w3s = (const float*)(smem + SM_W3);
            float* part = (float*)(smem + SM_PART);
            const float* qbb = g_qb + b * ND;
            int c0base = wc * 32 + (lane & 3) * 2;
            #pragma unroll
            for (int mt = 0; mt < 2; mt++) {
                float vlo = 0.0f, vhi = 0.0f;
                #pragma unroll
                for (int nt = 0; nt < 4; nt++) {
                    int c0 = c0base + nt * 8, c1 = c0 + 1;
                    float q0 = __ldg(qbb + c0), q1 = __ldg(qbb + c1);
                    float t0 = w3s[c0], t1 = w3s[c1];
                    vlo += fmaxf(acc[mt][nt][0] + q0, 0.0f) * t0
                         + fmaxf(acc[mt][nt][1] + q1, 0.0f) * t1;
                    vhi += fmaxf(acc[mt][nt][2] + q0, 0.0f) * t0
                         + fmaxf(acc[mt][nt][3] + q1, 0.0f) * t1;
                }
                vlo += __shfl_xor_sync(0xFFFFFFFFu, vlo, 1);
                vlo += __shfl_xor_sync(0xFFFFFFFFu, vlo, 2);
                vhi += __shfl_xor_sync(0xFFFFFFFFu, vhi, 1);
                vhi += __shfl_xor_sync(0xFFFFFFFFu, vhi, 2);
                if ((lane & 3) == 0) {
                    int rlo = wr * 32 + mt * 16 + (lane >> 2);
                    part[rlo * 4 + wc] = vlo;
                    part[(rlo + 8) * 4 + wc] = vhi;
                }
            }
        }
        __syncthreads();                            // part ready; ldsm of this tile done
        if (tid < 128) {
            const float* part = (const float*)(smem + SM_PART);
            float s = part[tid * 4] + part[tid * 4 + 1] + part[tid * 4 + 2] + part[tid * 4 + 3];
            g_scores[b * NL + l0 + tid] = s;
        }
        if (tn < NTILES) cvt_store(smem, v, tid);   // fill A for next tile
        t = tn;
    }
}

// ============ kernel 2: entmax bisection (candidate-compacted) + sparse sum ============
__global__ __launch_bounds__(512, 1)
void k_entmax(const float* __restrict__ R, const float* __restrict__ alpha,
              float* __restrict__ out) {
    __shared__ float cval[NL];
    __shared__ unsigned short cidx[NL];
    __shared__ float red[16];
    __shared__ int cnt;
    __shared__ float part[512];

    int b = blockIdx.x, t = threadIdx.x;
    int lane = t & 31, w = t >> 5;
    float am1 = alpha[b] - 1.0f;
    float inv = 1.0f / am1;

    if (t == 0) cnt = 0;

    float v[8];
    float mx = -3.4e38f;
    #pragma unroll
    for (int i = 0; i < 8; i++) {
        v[i] = g_scores[b * NL + t + i * 512] * am1;
        mx = fmaxf(mx, v[i]);
    }
    #pragma unroll
    for (int o = 16; o; o >>= 1) mx = fmaxf(mx, __shfl_xor_sync(0xFFFFFFFFu, mx, o));
    if (lane == 0) red[w] = mx;
    __syncthreads();
    mx = red[0];
    #pragma unroll
    for (int i = 1; i < 16; i++) mx = fmaxf(mx, red[i]);
    __syncthreads();

    float thr = mx - 1.0f;
    #pragma unroll
    for (int i = 0; i < 8; i++) {
        bool p = v[i] > thr;
        unsigned m = __ballot_sync(0xFFFFFFFFu, p);
        int base = 0;
        if (lane == 0 && m) base = atomicAdd(&cnt, __popc(m));
        base = __shfl_sync(0xFFFFFFFFu, base, 0);
        if (p) {
            int off = base + __popc(m & ((1u << lane) - 1u));
            cval[off] = v[i];
            cidx[off] = (unsigned short)(t + i * 512);
        }
    }
    __syncthreads();
    int K = cnt;

    float tau_lo = mx - 1.0f;
    float tau_hi = mx - exp2f(-12.0f * am1);
    float dm = tau_hi - tau_lo;

    float s = 0.0f;
    for (int j = t; j < K; j += 512) {
        float x = cval[j] - tau_lo;
        if (x > 0.0f) s += fast_pow(x, inv);
    }
    #pragma unroll
    for (int o = 16; o; o >>= 1) s += __shfl_xor_sync(0xFFFFFFFFu, s, o);
    if (lane == 0) red[w] = s;
    __syncthreads();
    float f_lo = -1.0f;
    #pragma unroll
    for (int i = 0; i < 16; i++) f_lo += red[i];
    __syncthreads();

    float tau_m = tau_lo;
    for (int it = 0; it < 50; it++) {
        dm *= 0.5f;
        tau_m = tau_lo + dm;
        s = 0.0f;
        for (int j = t; j < K; j += 512) {
            float x = cval[j] - tau_m;
            if (x > 0.0f) s += fast_pow(x, inv);
        }
        #pragma unroll
        for (int o = 16; o; o >>= 1) s += __shfl_xor_sync(0xFFFFFFFFu, s, o);
        if (lane == 0) red[w] = s;
        __syncthreads();
        float f_m = -1.0f;
        #pragma unroll
        for (int i = 0; i < 16; i++) f_m += red[i];
        __syncthreads();
        if (f_m * f_lo >= 0.0f) tau_lo = tau_m;
    }

    s = 0.0f;
    for (int j = t; j < K; j += 512) {
        float x = cval[j] - tau_m;
        float p = (x > 0.0f) ? fast_pow(x, inv) : 0.0f;
        cval[j] = p;
        s += p;
    }
    #pragma unroll
    for (int o = 16; o; o >>= 1) s += __shfl_xor_sync(0xFFFFFFFFu, s, o);
    if (lane == 0) red[w] = s;
    __syncthreads();
    float S = 0.0f;
    #pragma unroll
    for (int i = 0; i < 16; i++) S += red[i];
    __syncthreads();
    float invS = 1.0f / S;

    int gq = t >> 7, d = t & 127;
    const float* Rb = R + (size_t)b * NL * ND;
    float acc = 0.0f;
    for (int j = gq; j < K; j += 4) {
        float wv = cval[j];
        if (wv != 0.0f) {
            int l = cidx[j];
            acc += wv * Rb[(size_t)l * ND + d];
        }
    }
    part[t] = acc;
    __syncthreads();

    float myr = 0.0f;
    if (t < ND) {
        float r = (part[t] + part[128 + t] + part[256 + t] + part[384 + t]) * invS;
        float e = (r > 0.0f) ? r : 1.6732632423543772f * expm1f(r);
        myr = 1.0507009873554805f * e;
    }
    float nsq = myr * myr;
    #pragma unroll
    for (int o = 16; o; o >>= 1) nsq += __shfl_xor_sync(0xFFFFFFFFu, nsq, o);
    if (lane == 0) red[w] = nsq;
    __syncthreads();
    float tot = 0.0f;
    #pragma unroll
    for (int i = 0; i < 16; i++) tot += red[i];
    if (t < ND) out[b * ND + t] = myr / sqrtf(tot);
}

// ============ launch ============
extern "C" void kernel_launch(void* const* d_in, const int* in_sizes, int n_in,
                              void* d_out, int out_size) {
    const float* R      = (const float*)d_in[0];
    const float* alpha  = (const float*)d_in[1];
    const float* target = (const float*)d_in[2];
    const float* Wr1    = (const float*)d_in[3];
    const float* Wr2    = (const float*)d_in[4];
    const float* Wr3    = (const float*)d_in[5];
    const float* bias_r = (const float*)d_in[6];
    const float* Wf_w   = (const float*)d_in[7];
    const float* Wf_b   = (const float*)d_in[8];
    float* out = (float*)d_out;

    int nsm = 0;
    cudaDeviceGetAttribute(&nsm, cudaDevAttrMultiProcessorCount, 0);
    if (nsm <= 0) nsm = 148;

    cudaFuncSetAttribute(k_gemm, cudaFuncAttributeMaxDynamicSharedMemorySize, SM_TOTAL);

    k_prep<<<NB, 512>>>(target, Wf_w, Wf_b, Wr2, bias_r);
    k_gemm<<<nsm, 512, SM_TOTAL>>>(R, Wr1, Wr3);
    k_entmax<<<NB, 512>>>(R, alpha, out);
}